// round 16
// baseline (speedup 1.0000x reference)
#include <cuda_runtime.h>
#include <cstdint>
#include <math.h>

#define BN 2048
#define DN 3072
#define CN 10
#define MN 9
#define NBLK 128

#define ALPHA  0.999999f             // 1 - C*NUM_STAB
#define NST    1e-7f
#define RS10   0.31622776601683794f  // 1/sqrt(10)

typedef unsigned long long u64;
typedef unsigned int u32;

// packed fp32x2 FMA: acc.{lo,hi} += a.{lo,hi} * b.{lo,hi}
#define FMA_X2(acc, a, b) \
    asm("fma.rn.f32x2 %0, %1, %2, %0;" : "+l"(acc) : "l"(a), "l"(b))
#define UNPACK_X2(lo, hi, v) \
    asm("mov.b64 {%0, %1}, %2;" : "=f"(lo), "=f"(hi) : "l"(v))

#define MBAR_INIT(a, n) \
    asm volatile("mbarrier.init.shared.b64 [%0], %1;" :: "r"(a), "r"(n) : "memory")
#define MBAR_EXPECT_TX(a, n) \
    asm volatile("mbarrier.arrive.expect_tx.shared.b64 _, [%0], %1;" :: "r"(a), "r"(n) : "memory")
#define CP_BULK_CTA(dst, src, bytes, mbar) \
    asm volatile("cp.async.bulk.shared::cta.global.mbarrier::complete_tx::bytes [%0], [%1], %2, [%3];" \
        :: "r"(dst), "l"(src), "r"(bytes), "r"(mbar) : "memory")

__device__ __forceinline__ void mbar_wait(u32 mbar, u32 parity) {
    u32 done;
    asm volatile(
        "{\n\t.reg .pred p;\n\t"
        "mbarrier.try_wait.parity.acquire.cta.shared::cta.b64 p, [%1], %2;\n\t"
        "selp.b32 %0, 1, 0, p;\n\t}"
        : "=r"(done) : "r"(mbar), "r"(parity) : "memory");
    if (!done) {
        asm volatile(
            "{\n\t.reg .pred P1;\n\t"
            "WL%=:\n\t"
            "mbarrier.try_wait.parity.acquire.cta.shared::cta.b64 P1, [%0], %1, 0x989680;\n\t"
            "@P1 bra.uni WD%=;\n\t"
            "bra.uni WL%=;\n\t"
            "WD%=:\n\t}"
            :: "r"(mbar), "r"(parity) : "memory");
    }
}

// Scratch (no allocations allowed). Zero-initialized at process start; flags
// reset by the last block each launch for graph-replay determinism.
__device__ __align__(16) float g_Wt[CN * DN];    // W transposed [C][D]
__device__ float g_WgP[NBLK * CN * CN];          // per-block Wg partials
__device__ float g_Wg[CN * CN];                  // aggregated W^T W
__device__ int g_f1;                             // Wt+partials done counter
__device__ int g_f2;                             // Wg aggregated flag
__device__ int g_fin;                            // completion counter (reset)

// ---------------------------------------------------------------------------
// Single fused kernel: 128 blocks x 512 threads, 16 samples/block.
// Phase 0: issue TMA x-fill (samples 0-7, 8x12KB) immediately.
// Phase 1 (overlapped with TMA): cooperative W prep — each block transposes
//   its 24 W rows into g_Wt + writes a Wg partial; grid-sync via g_f1
//   (all 128 blocks co-resident -> spin is safe). Block 0 aggregates g_Wg
//   behind g_f2 (checked only at epilogue, ~12us later).
// Phase 2: R9 compute — warps 0-7 FFMA2 from SMEM (TMA half), warps 8-15
//   stream samples 8-15 via ld.global.cs (LSU engine parallel with TMA),
//   W via __ldg on g_Wt.
// Phase 3: fused epilogue; last block resets flags.
// ---------------------------------------------------------------------------
extern __shared__ __align__(16) float4 xsm[];    // [8 samples][768 float4] = 96KB

__global__ void __launch_bounds__(512, 1) main_kernel(const float* __restrict__ data,
                                                      const float* __restrict__ W,
                                                      const float* __restrict__ bias,
                                                      float* __restrict__ out) {
    __shared__ __align__(8) u64 mbar_s;
    __shared__ float smred[8][16][CN];           // [kidx][sample][class]

    const int tid   = threadIdx.x;
    const int wid   = tid >> 5;
    const int lane  = tid & 31;
    const int kidx  = wid & 7;                   // K-eighth (96 float4)
    const int octet = wid >> 3;                  // 0 = TMA half, 1 = LDG half
    const int pgrp  = lane >> 3;                 // sample pair within half
    const int klane = lane & 7;
    const int bid   = blockIdx.x;

    const int ls = pgrp * 2;                     // local sample within half
    const int s0 = bid * 16;                     // block's first sample

    const char* blk = reinterpret_cast<const char*>(data) + (size_t)s0 * (DN * 4);

    const u32 mbar = (u32)__cvta_generic_to_shared(&mbar_s);
    const u32 xsa  = (u32)__cvta_generic_to_shared(xsm);

    if (tid == 0) MBAR_INIT(mbar, 1);
    __syncthreads();

    // ---- phase 0: TMA x staging (independent of W) -------------------------
    if (tid == 0) {
        MBAR_EXPECT_TX(mbar, 98304u);
        #pragma unroll
        for (int j = 0; j < 8; j++)
            CP_BULK_CTA(xsa + j * 12288u, blk + (size_t)j * 12288u, 12288u, mbar);
    }

    // ---- phase 1: cooperative W prep (overlaps TMA fill) -------------------
    {
        const float* wb = W + bid * 240;         // this block's 24 rows
        if (tid < 240) {
            float v = __ldg(&wb[tid]);           // coalesced: W[bid*240 + tid]
            int dd = tid / 10;
            int cc = tid - dd * 10;
            g_Wt[cc * DN + (bid * 24 + dd)] = v;
        }
        if (tid < 100) {
            int i = tid / 10, j = tid - (tid / 10) * 10;
            float acc = 0.f;
            #pragma unroll
            for (int d = 0; d < 24; d++)
                acc = fmaf(__ldg(&wb[d * 10 + i]), __ldg(&wb[d * 10 + j]), acc);
            g_WgP[bid * 100 + tid] = acc;
        }
        __threadfence();
        __syncthreads();
        if (tid == 0) atomicAdd(&g_f1, 1);
    }

    // block 0 aggregates Wg (fixed order -> deterministic)
    if (bid == 0) {
        if (tid == 0) { while (atomicAdd(&g_f1, 0) < NBLK) {} __threadfence(); }
        __syncthreads();
        if (tid < 100) {
            float s = 0.f;
            #pragma unroll 8
            for (int b = 0; b < NBLK; b++) s += g_WgP[b * 100 + tid];
            g_Wg[tid] = s;
        }
        __threadfence();
        __syncthreads();
        if (tid == 0) atomicExch(&g_f2, 1);
    }

    // all blocks: wait for full Wt before compute
    if (tid == 0) { while (atomicAdd(&g_f1, 0) < NBLK) {} __threadfence(); }
    __syncthreads();

    // ---- phase 2: R9 compute ------------------------------------------------
    const ulonglong2* __restrict__ wt = reinterpret_cast<const ulonglong2*>(g_Wt);
    const int kw = kidx * 96 + klane;            // W float4 base index

    u64 a0[CN], a1[CN];
    #pragma unroll
    for (int c = 0; c < CN; c++) { a0[c] = 0ull; a1[c] = 0ull; }

    if (octet == 0) {
        mbar_wait(mbar, 0);
        const ulonglong2* __restrict__ xs = reinterpret_cast<const ulonglong2*>(xsm);
        const ulonglong2* __restrict__ x0 = xs + (size_t)ls * 768 + kw;
        #pragma unroll
        for (int i = 0; i < 12; i++) {
            ulonglong2 xv0 = x0[i * 8];
            ulonglong2 xv1 = x0[768 + i * 8];
            #pragma unroll
            for (int c = 0; c < CN; c++) {
                ulonglong2 wv = __ldg(&wt[c * 768 + kw + i * 8]);
                FMA_X2(a0[c], xv0.x, wv.x);
                FMA_X2(a0[c], xv0.y, wv.y);
                FMA_X2(a1[c], xv1.x, wv.x);
                FMA_X2(a1[c], xv1.y, wv.y);
            }
        }
    } else {
        const char* xb0 = blk + (size_t)(8 + ls) * (DN * 4);
        const char* xb1 = xb0 + DN * 4;
        #pragma unroll 4
        for (int i = 0; i < 12; i++) {
            int k4 = kw + i * 8;
            u64 x0lo, x0hi, x1lo, x1hi;
            asm("ld.global.cs.v2.u64 {%0, %1}, [%2];"
                : "=l"(x0lo), "=l"(x0hi) : "l"(xb0 + (size_t)k4 * 16));
            asm("ld.global.cs.v2.u64 {%0, %1}, [%2];"
                : "=l"(x1lo), "=l"(x1hi) : "l"(xb1 + (size_t)k4 * 16));
            #pragma unroll
            for (int c = 0; c < CN; c++) {
                ulonglong2 wv = __ldg(&wt[c * 768 + kw + i * 8]);
                FMA_X2(a0[c], x0lo, wv.x);
                FMA_X2(a0[c], x0hi, wv.y);
                FMA_X2(a1[c], x1lo, wv.x);
                FMA_X2(a1[c], x1hi, wv.y);
            }
        }
    }

    // unpack, reduce across 8 klanes (xor 1,2,4 stay within pgrp)
    float f0[CN], f1[CN];
    #pragma unroll
    for (int c = 0; c < CN; c++) {
        float lo, hi;
        UNPACK_X2(lo, hi, a0[c]); f0[c] = lo + hi;
        UNPACK_X2(lo, hi, a1[c]); f1[c] = lo + hi;
    }
    #pragma unroll
    for (int c = 0; c < CN; c++) {
        #pragma unroll
        for (int off = 4; off > 0; off >>= 1) {
            f0[c] += __shfl_xor_sync(0xffffffffu, f0[c], off);
            f1[c] += __shfl_xor_sync(0xffffffffu, f1[c], off);
        }
    }
    if (klane == 0) {
        int srow = octet * 8 + ls;
        #pragma unroll
        for (int c = 0; c < CN; c++) {
            smred[kidx][srow][c]     = f0[c];
            smred[kidx][srow + 1][c] = f1[c];
        }
    }

    // ensure g_Wg is ready (set at ~4us; we arrive here ~12us later)
    if (tid == 0) { while (atomicAdd(&g_f2, 0) == 0) {} __threadfence(); }
    __syncthreads();

    // ---- phase 3: fused epilogue: 16 threads, one per sample ---------------
    if (tid < 16) {
        float l[CN];
        #pragma unroll
        for (int c = 0; c < CN; c++) {
            float a = __ldg(&bias[c]);
            #pragma unroll
            for (int k = 0; k < 8; k++) a += smred[k][tid][c];
            l[c] = a;
        }

        float mx = l[0];
        #pragma unroll
        for (int c = 1; c < CN; c++) mx = fmaxf(mx, l[c]);

        float e[CN], Z = 0.f;
        #pragma unroll
        for (int c = 0; c < CN; c++) { e[c] = expf(l[c] - mx); Z += e[c]; }
        float invZ = 1.f / Z;

        float s[CN], r[CN], sumr = 0.f;
        #pragma unroll
        for (int c = 0; c < CN; c++) {
            s[c] = e[c] * invZ;
            float p = fmaf(s[c], ALPHA, NST);
            r[c] = sqrtf(p);
            sumr += r[c];
        }
        float u = 1.f - r[MN];
        float delta = 2.f * acosf(fminf(sumr * RS10, 1.f));

        float wg[CN * CN];
        #pragma unroll
        for (int v = 0; v < CN * CN; v++) wg[v] = g_Wg[v];

        float q[CN];
        #pragma unroll
        for (int j = 0; j < CN; j++) {
            float a = 0.f;
            #pragma unroll
            for (int k = 0; k < CN; k++) a = fmaf(s[k], wg[k * CN + j], a);
            q[j] = a;
        }
        float qs = 0.f;
        #pragma unroll
        for (int j = 0; j < CN; j++) qs = fmaf(q[j], s[j], qs);

        float inv_u = 1.f / u;
        float c2com = ALPHA * s[MN] * inv_u * inv_u / r[MN];
        float c1[MN], c2[MN], t[MN];
        #pragma unroll
        for (int m = 0; m < MN; m++) {
            c1[m] = ALPHA * s[m] * inv_u / r[m];
            c2[m] = c2com * r[m];
            t[m]  = c1[m] + c2[m];
        }

        float col[MN];
        #pragma unroll
        for (int n = 0; n < MN; n++) col[n] = 0.f;
        float norminf = 0.f;

        #pragma unroll
        for (int m = 0; m < MN; m++) {
            float Mrow[CN];
            #pragma unroll
            for (int j = 0; j < CN; j++)
                Mrow[j] = c1[m] * wg[m * CN + j] + c2[m] * wg[MN * CN + j] - t[m] * q[j];
            float wm = c1[m] * q[m] + c2[m] * q[MN] - t[m] * qs;
            float rowsum = 0.f;
            #pragma unroll
            for (int n = 0; n < MN; n++) {
                float g2 = c1[n] * Mrow[n] + c2[n] * Mrow[MN] - t[n] * wm;
                float ag = fabsf(g2);
                rowsum += ag;
                col[n] += ag;
            }
            norminf = fmaxf(norminf, rowsum);
        }
        float norm1 = 0.f;
        #pragma unroll
        for (int n = 0; n < MN; n++) norm1 = fmaxf(norm1, col[n]);

        float u2 = u * u;
        float jn = u2 * sqrtf(norm1 * norminf);
        out[s0 + tid] = delta / (0.1f * jn);
    }

    // ---- reset flags for the next graph replay (last block only) -----------
    __syncthreads();
    if (tid == 0) {
        int v = atomicAdd(&g_fin, 1);
        if (v == NBLK - 1) {
            g_fin = 0;
            g_f1  = 0;
            g_f2  = 0;
            __threadfence();
        }
    }
}

// ---------------------------------------------------------------------------
extern "C" void kernel_launch(void* const* d_in, const int* in_sizes, int n_in,
                              void* d_out, int out_size) {
    const float* data = (const float*)d_in[0];   // [2048,3,32,32]
    const float* W    = (const float*)d_in[1];   // [3072,10]
    const float* bias = (const float*)d_in[2];   // [10]
    float* out = (float*)d_out;                  // [2048,1]

    static int configured = 0;
    if (!configured) {
        cudaFuncSetAttribute(main_kernel,
                             cudaFuncAttributeMaxDynamicSharedMemorySize,
                             98304 + 10240);
        configured = 1;
    }

    main_kernel<<<NBLK, 512, 98304>>>(data, W, bias, out);
}

// round 17
// speedup vs baseline: 1.3361x; 1.3361x over previous
#include <cuda_runtime.h>
#include <cstdint>
#include <math.h>

#define BN 2048
#define DN 3072
#define CN 10
#define MN 9

#define ALPHA  0.999999f             // 1 - C*NUM_STAB
#define NST    1e-7f
#define RS10   0.31622776601683794f  // 1/sqrt(10)

typedef unsigned long long u64;
typedef unsigned int u32;

// packed fp32x2 FMA: acc.{lo,hi} += a.{lo,hi} * b.{lo,hi}
#define FMA_X2(acc, a, b) \
    asm("fma.rn.f32x2 %0, %1, %2, %0;" : "+l"(acc) : "l"(a), "l"(b))
#define UNPACK_X2(lo, hi, v) \
    asm("mov.b64 {%0, %1}, %2;" : "=f"(lo), "=f"(hi) : "l"(v))

#define MBAR_INIT(a, n) \
    asm volatile("mbarrier.init.shared.b64 [%0], %1;" :: "r"(a), "r"(n) : "memory")
#define MBAR_EXPECT_TX(a, n) \
    asm volatile("mbarrier.arrive.expect_tx.shared.b64 _, [%0], %1;" :: "r"(a), "r"(n) : "memory")
#define CP_BULK_CTA(dst, src, bytes, mbar) \
    asm volatile("cp.async.bulk.shared::cta.global.mbarrier::complete_tx::bytes [%0], [%1], %2, [%3];" \
        :: "r"(dst), "l"(src), "r"(bytes), "r"(mbar) : "memory")

// PDL controls
#define GRIDDEP_WAIT() \
    asm volatile("griddepcontrol.wait;" ::: "memory")
#define GRIDDEP_LAUNCH_DEPENDENTS() \
    asm volatile("griddepcontrol.launch_dependents;" ::: "memory")

__device__ __forceinline__ void mbar_wait(u32 mbar, u32 parity) {
    u32 done;
    asm volatile(
        "{\n\t.reg .pred p;\n\t"
        "mbarrier.try_wait.parity.acquire.cta.shared::cta.b64 p, [%1], %2;\n\t"
        "selp.b32 %0, 1, 0, p;\n\t}"
        : "=r"(done) : "r"(mbar), "r"(parity) : "memory");
    if (!done) {
        asm volatile(
            "{\n\t.reg .pred P1;\n\t"
            "WL%=:\n\t"
            "mbarrier.try_wait.parity.acquire.cta.shared::cta.b64 P1, [%0], %1, 0x989680;\n\t"
            "@P1 bra.uni WD%=;\n\t"
            "bra.uni WL%=;\n\t"
            "WD%=:\n\t}"
            :: "r"(mbar), "r"(parity) : "memory");
    }
}

// Scratch (no allocations allowed)
__device__ __align__(16) float g_Wt[CN * DN];    // W transposed [C][D]
__device__ float g_Wg[CN * CN];                  // W^T W

// ---------------------------------------------------------------------------
// Prep: blocks 0..11 transpose W -> Wt; blocks 12..21 compute Wg rows.
// Each CTA signals launch_dependents after its writes are fenced, letting
// the PDL-launched main kernel proceed as early as possible.
// ---------------------------------------------------------------------------
__global__ void __launch_bounds__(256) prep_kernel(const float* __restrict__ W) {
    int bid = blockIdx.x;
    int tid = threadIdx.x;
    if (bid < 12) {
        int d = bid * 256 + tid;
        float w[CN];
        #pragma unroll
        for (int c = 0; c < CN; c++) w[c] = __ldg(&W[d * CN + c]);
        #pragma unroll
        for (int c = 0; c < CN; c++) g_Wt[c * DN + d] = w[c];
        __threadfence();
        __syncthreads();
        if (tid == 0) GRIDDEP_LAUNCH_DEPENDENTS();
    } else {
        int i = bid - 12;
        float acc[CN];
        #pragma unroll
        for (int j = 0; j < CN; j++) acc[j] = 0.f;
        for (int d = tid; d < DN; d += 256) {
            float w[CN];
            #pragma unroll
            for (int j = 0; j < CN; j++) w[j] = __ldg(&W[d * CN + j]);
            float wi = w[i];
            #pragma unroll
            for (int j = 0; j < CN; j++) acc[j] = fmaf(wi, w[j], acc[j]);
        }
        #pragma unroll
        for (int j = 0; j < CN; j++) {
            #pragma unroll
            for (int off = 16; off > 0; off >>= 1)
                acc[j] += __shfl_xor_sync(0xffffffffu, acc[j], off);
        }
        __shared__ float smem[8][CN];
        int w_ = tid >> 5, l = tid & 31;
        if (l == 0) {
            #pragma unroll
            for (int j = 0; j < CN; j++) smem[w_][j] = acc[j];
        }
        __syncthreads();
        if (tid < CN) {
            float s = 0.f;
            #pragma unroll
            for (int k = 0; k < 8; k++) s += smem[k][tid];
            g_Wg[i * CN + tid] = s;
        }
        __threadfence();
        __syncthreads();
        if (tid == 0) GRIDDEP_LAUNCH_DEPENDENTS();
    }
}

// ---------------------------------------------------------------------------
// Hybrid main kernel (R9-exact compute) launched with PDL: starts while prep
// is in flight, issues TMA x staging immediately (independent of W), then
// griddepcontrol.wait before touching g_Wt / g_Wg.
// 128 blocks x 512 threads, 16 samples/block.
// Samples 0-7: TMA bulk -> smem (8 x 12KB, one mbarrier), warps 0-7.
// Samples 8-15: direct ld.global.cs, warps 8-15. FFMA2, fused epilogue.
// ---------------------------------------------------------------------------
extern __shared__ __align__(16) float4 xsm[];    // [8 samples][768 float4] = 96KB

__global__ void __launch_bounds__(512, 1) main_kernel(const float* __restrict__ data,
                                                      const float* __restrict__ bias,
                                                      float* __restrict__ out) {
    __shared__ __align__(8) u64 mbar_s;
    __shared__ float smred[8][16][CN];           // [kidx][sample][class]

    const int tid   = threadIdx.x;
    const int wid   = tid >> 5;
    const int lane  = tid & 31;
    const int kidx  = wid & 7;                   // K-eighth (96 float4)
    const int octet = wid >> 3;                  // 0 = TMA half, 1 = LDG half
    const int pgrp  = lane >> 3;                 // sample pair within half
    const int klane = lane & 7;

    const int ls = pgrp * 2;                     // local sample within half
    const int s0 = blockIdx.x * 16;              // block's first sample

    const char* blk = reinterpret_cast<const char*>(data) + (size_t)s0 * (DN * 4);

    const u32 mbar = (u32)__cvta_generic_to_shared(&mbar_s);
    const u32 xsa  = (u32)__cvta_generic_to_shared(xsm);

    if (tid == 0) MBAR_INIT(mbar, 1);
    __syncthreads();

    // ---- TMA x staging: independent of prep, issue before the PDL wait ----
    if (tid == 0) {
        MBAR_EXPECT_TX(mbar, 98304u);
        #pragma unroll
        for (int j = 0; j < 8; j++)
            CP_BULK_CTA(xsa + j * 12288u, blk + (size_t)j * 12288u, 12288u, mbar);
    }

    // ---- wait for prep's Wt/Wg writes (PDL HW barrier) ---------------------
    GRIDDEP_WAIT();

    const ulonglong2* __restrict__ wt = reinterpret_cast<const ulonglong2*>(g_Wt);
    const int kw = kidx * 96 + klane;            // W float4 base index

    u64 a0[CN], a1[CN];
    #pragma unroll
    for (int c = 0; c < CN; c++) { a0[c] = 0ull; a1[c] = 0ull; }

    if (octet == 0) {
        // ---- TMA half: wait for smem fill, compute from SMEM --------------
        mbar_wait(mbar, 0);
        const ulonglong2* __restrict__ xs = reinterpret_cast<const ulonglong2*>(xsm);
        const ulonglong2* __restrict__ x0 = xs + (size_t)ls * 768 + kw;
        #pragma unroll
        for (int i = 0; i < 12; i++) {
            ulonglong2 xv0 = x0[i * 8];
            ulonglong2 xv1 = x0[768 + i * 8];
            #pragma unroll
            for (int c = 0; c < CN; c++) {
                ulonglong2 wv = __ldg(&wt[c * 768 + kw + i * 8]);
                FMA_X2(a0[c], xv0.x, wv.x);
                FMA_X2(a0[c], xv0.y, wv.y);
                FMA_X2(a1[c], xv1.x, wv.x);
                FMA_X2(a1[c], xv1.y, wv.y);
            }
        }
    } else {
        // ---- LDG half: stream directly from gmem (LSU engine) -------------
        const char* xb0 = blk + (size_t)(8 + ls) * (DN * 4);
        const char* xb1 = xb0 + DN * 4;
        #pragma unroll 4
        for (int i = 0; i < 12; i++) {
            int k4 = kw + i * 8;
            u64 x0lo, x0hi, x1lo, x1hi;
            asm("ld.global.cs.v2.u64 {%0, %1}, [%2];"
                : "=l"(x0lo), "=l"(x0hi) : "l"(xb0 + (size_t)k4 * 16));
            asm("ld.global.cs.v2.u64 {%0, %1}, [%2];"
                : "=l"(x1lo), "=l"(x1hi) : "l"(xb1 + (size_t)k4 * 16));
            #pragma unroll
            for (int c = 0; c < CN; c++) {
                ulonglong2 wv = __ldg(&wt[c * 768 + kw + i * 8]);
                FMA_X2(a0[c], x0lo, wv.x);
                FMA_X2(a0[c], x0hi, wv.y);
                FMA_X2(a1[c], x1lo, wv.x);
                FMA_X2(a1[c], x1hi, wv.y);
            }
        }
    }

    // unpack, reduce across 8 klanes (xor 1,2,4 stay within pgrp)
    float f0[CN], f1[CN];
    #pragma unroll
    for (int c = 0; c < CN; c++) {
        float lo, hi;
        UNPACK_X2(lo, hi, a0[c]); f0[c] = lo + hi;
        UNPACK_X2(lo, hi, a1[c]); f1[c] = lo + hi;
    }
    #pragma unroll
    for (int c = 0; c < CN; c++) {
        #pragma unroll
        for (int off = 4; off > 0; off >>= 1) {
            f0[c] += __shfl_xor_sync(0xffffffffu, f0[c], off);
            f1[c] += __shfl_xor_sync(0xffffffffu, f1[c], off);
        }
    }
    if (klane == 0) {
        int srow = octet * 8 + ls;
        #pragma unroll
        for (int c = 0; c < CN; c++) {
            smred[kidx][srow][c]     = f0[c];
            smred[kidx][srow + 1][c] = f1[c];
        }
    }
    __syncthreads();

    // ---- fused epilogue: 16 threads, one per sample ------------------------
    if (tid < 16) {
        float l[CN];
        #pragma unroll
        for (int c = 0; c < CN; c++) {
            float a = __ldg(&bias[c]);
            #pragma unroll
            for (int k = 0; k < 8; k++) a += smred[k][tid][c];
            l[c] = a;
        }

        float mx = l[0];
        #pragma unroll
        for (int c = 1; c < CN; c++) mx = fmaxf(mx, l[c]);

        float e[CN], Z = 0.f;
        #pragma unroll
        for (int c = 0; c < CN; c++) { e[c] = expf(l[c] - mx); Z += e[c]; }
        float invZ = 1.f / Z;

        float s[CN], r[CN], sumr = 0.f;
        #pragma unroll
        for (int c = 0; c < CN; c++) {
            s[c] = e[c] * invZ;
            float p = fmaf(s[c], ALPHA, NST);
            r[c] = sqrtf(p);
            sumr += r[c];
        }
        float u = 1.f - r[MN];
        float delta = 2.f * acosf(fminf(sumr * RS10, 1.f));

        float wg[CN * CN];
        #pragma unroll
        for (int v = 0; v < CN * CN; v++) wg[v] = __ldg(&g_Wg[v]);

        float q[CN];
        #pragma unroll
        for (int j = 0; j < CN; j++) {
            float a = 0.f;
            #pragma unroll
            for (int k = 0; k < CN; k++) a = fmaf(s[k], wg[k * CN + j], a);
            q[j] = a;
        }
        float qs = 0.f;
        #pragma unroll
        for (int j = 0; j < CN; j++) qs = fmaf(q[j], s[j], qs);

        float inv_u = 1.f / u;
        float c2com = ALPHA * s[MN] * inv_u * inv_u / r[MN];
        float c1[MN], c2[MN], t[MN];
        #pragma unroll
        for (int m = 0; m < MN; m++) {
            c1[m] = ALPHA * s[m] * inv_u / r[m];
            c2[m] = c2com * r[m];
            t[m]  = c1[m] + c2[m];
        }

        float col[MN];
        #pragma unroll
        for (int n = 0; n < MN; n++) col[n] = 0.f;
        float norminf = 0.f;

        #pragma unroll
        for (int m = 0; m < MN; m++) {
            float Mrow[CN];
            #pragma unroll
            for (int j = 0; j < CN; j++)
                Mrow[j] = c1[m] * wg[m * CN + j] + c2[m] * wg[MN * CN + j] - t[m] * q[j];
            float wm = c1[m] * q[m] + c2[m] * q[MN] - t[m] * qs;
            float rowsum = 0.f;
            #pragma unroll
            for (int n = 0; n < MN; n++) {
                float g2 = c1[n] * Mrow[n] + c2[n] * Mrow[MN] - t[n] * wm;
                float ag = fabsf(g2);
                rowsum += ag;
                col[n] += ag;
            }
            norminf = fmaxf(norminf, rowsum);
        }
        float norm1 = 0.f;
        #pragma unroll
        for (int n = 0; n < MN; n++) norm1 = fmaxf(norm1, col[n]);

        float u2 = u * u;
        float jn = u2 * sqrtf(norm1 * norminf);
        out[s0 + tid] = delta / (0.1f * jn);
    }
}

// ---------------------------------------------------------------------------
extern "C" void kernel_launch(void* const* d_in, const int* in_sizes, int n_in,
                              void* d_out, int out_size) {
    const float* data = (const float*)d_in[0];   // [2048,3,32,32]
    const float* W    = (const float*)d_in[1];   // [3072,10]
    const float* bias = (const float*)d_in[2];   // [10]
    float* out = (float*)d_out;                  // [2048,1]

    static int configured = 0;
    if (!configured) {
        cudaFuncSetAttribute(main_kernel,
                             cudaFuncAttributeMaxDynamicSharedMemorySize,
                             98304 + 10240);
        configured = 1;
    }

    prep_kernel<<<22, 256>>>(W);

    // PDL launch: main may begin while prep is in flight; it gates itself
    // with griddepcontrol.wait before reading g_Wt / g_Wg.
    cudaLaunchConfig_t cfg = {};
    cfg.gridDim  = dim3(128, 1, 1);
    cfg.blockDim = dim3(512, 1, 1);
    cfg.dynamicSmemBytes = 98304;
    cfg.stream = 0;
    cudaLaunchAttribute attrs[1];
    attrs[0].id = cudaLaunchAttributeProgrammaticStreamSerialization;
    attrs[0].val.programmaticStreamSerializationAllowed = 1;
    cfg.attrs = attrs;
    cfg.numAttrs = 1;
    cudaLaunchKernelEx(&cfg, main_kernel, data, bias, out);
}